// round 2
// baseline (speedup 1.0000x reference)
#include <cuda_runtime.h>
#include <math.h>

#define BB   8
#define NN   512
#define TT   64
#define NIN  64
#define NE   128
#define NH2  128
#define NZ   512
#define NODES (BB*NN)          // 4096

// ---- persistent device scratch (static allocation is allowed) ----
__device__ float g_An[BB*NN*NN];        // 8 MB normalized adjacency
__device__ float g_dinv[BB*NN];
__device__ float g_es[NODES*NE];        // 2 MB
__device__ float g_esW[NODES*NZ];       // 8 MB  step-invariant gate term (packed cols)
__device__ float g_Wc[NE*NZ];           // 256 KB  Wpe @ Wcat (packed)
__device__ float g_Wh2[NH2*NZ];         // 256 KB  h-path gate weights (packed)
__device__ float g_b0[NZ];
__device__ float g_h[2][NODES*NH2];     // ping-pong hidden state
__device__ float g_c[NODES*NH2];

// ---- packed fp32x2 helpers (B300: FFMA2 doubles fp32 MAC rate) ----
__device__ __forceinline__ void fma2(unsigned long long &d, unsigned long long a,
                                     unsigned long long b) {
    asm("fma.rn.f32x2 %0, %1, %2, %3;" : "=l"(d) : "l"(a), "l"(b), "l"(d));
}
__device__ __forceinline__ unsigned long long pack2(float x) {
    unsigned long long r; asm("mov.b64 %0, {%1, %1};" : "=l"(r) : "f"(x)); return r;
}
__device__ __forceinline__ float2 unpack2(unsigned long long v) {
    float2 r; asm("mov.b64 {%0, %1}, %2;" : "=f"(r.x), "=f"(r.y) : "l"(v)); return r;
}

// ---------------- setup kernels ----------------

__global__ void k_dinv(const float* __restrict__ A) {
    int row = blockIdx.x;                       // b*NN + n
    const float* ap = A + (size_t)row * NN;
    float s = 0.f;
    for (int i = threadIdx.x; i < NN; i += 128) s += ap[i];
    __shared__ float red[4];
    for (int o = 16; o; o >>= 1) s += __shfl_xor_sync(0xffffffffu, s, o);
    if ((threadIdx.x & 31) == 0) red[threadIdx.x >> 5] = s;
    __syncthreads();
    if (threadIdx.x == 0) {
        float d = red[0] + red[1] + red[2] + red[3];
        g_dinv[row] = d > 0.f ? rsqrtf(d) : 0.f;
    }
}

__global__ void k_an(const float* __restrict__ A) {
    int idx = blockIdx.x * 256 + threadIdx.x;   // BB*NN*NN threads
    int b = idx / (NN * NN);
    int r = (idx / NN) % NN;
    int m = idx % NN;
    g_An[idx] = A[idx] * g_dinv[b * NN + r] * g_dinv[b * NN + m];
}

__global__ void k_es(const float* __restrict__ X, const float* __restrict__ Wse,
                     const float* __restrict__ bse, float* __restrict__ out) {
    int idx = blockIdx.x * 256 + threadIdx.x;   // NODES*NE threads
    int node = idx >> 7, j = idx & 127;
    const float* x0 = X + (size_t)node * TT * NIN;   // X[b][n][0][:]
    float acc = bse[j];
    #pragma unroll
    for (int q = 0; q < NIN; q++) acc += x0[q] * Wse[q * NE + j];
    g_es[idx] = acc;
    if (j < NIN) out[(size_t)node * TT * NIN + j] = x0[j];   // out[...,0,:] = X0
}

__global__ void k_wpack(const float* __restrict__ Wpe, const float* __restrict__ bpe,
    const float* __restrict__ Wii, const float* __restrict__ bii,
    const float* __restrict__ Whi, const float* __restrict__ bhi,
    const float* __restrict__ Wif, const float* __restrict__ bif,
    const float* __restrict__ Whf, const float* __restrict__ bhf,
    const float* __restrict__ Wig, const float* __restrict__ big,
    const float* __restrict__ Whg, const float* __restrict__ bhg,
    const float* __restrict__ Wio, const float* __restrict__ bio,
    const float* __restrict__ Who, const float* __restrict__ bho) {
    int idx = blockIdx.x * 256 + threadIdx.x;   // NE*NZ threads
    int k = idx >> 9, j = idx & 511;
    int ch = j >> 2, g = j & 3;
    const float* Wg  = g == 0 ? Wii : g == 1 ? Wif : g == 2 ? Wig : Wio;
    const float* Whg_ = g == 0 ? Whi : g == 1 ? Whf : g == 2 ? Whg : Who;
    float acc = 0.f;
    for (int p = 0; p < NE; p++) acc += Wpe[k * NE + p] * Wg[(NE + p) * NH2 + ch];
    g_Wc[idx]  = acc;
    g_Wh2[idx] = Whg_[k * NH2 + ch];
    if (k == 0) {
        const float* bg  = g == 0 ? bii : g == 1 ? bif : g == 2 ? big : bio;
        const float* bhg2 = g == 0 ? bhi : g == 1 ? bhf : g == 2 ? bhg : bho;
        float bv = bg[ch] + bhg2[ch];
        for (int p = 0; p < NE; p++) bv += bpe[p] * Wg[(NE + p) * NH2 + ch];
        g_b0[j] = bv;
    }
}

__global__ void k_esw(const float* __restrict__ Wii, const float* __restrict__ Wif,
                      const float* __restrict__ Wig, const float* __restrict__ Wio) {
    int idx = blockIdx.x * 256 + threadIdx.x;   // NODES*NZ threads
    int node = idx >> 9, j = idx & 511;
    int ch = j >> 2, g = j & 3;
    const float* Wg = g == 0 ? Wii : g == 1 ? Wif : g == 2 ? Wig : Wio;
    const float* e = g_es + (size_t)node * NE;
    float acc = g_b0[j];
    for (int p = 0; p < NE; p++) acc += e[p] * Wg[p * NH2 + ch];
    g_esW[idx] = acc;
}

__global__ void k_zero() {
    int idx = blockIdx.x * 256 + threadIdx.x;   // NODES*NH2 threads
    g_h[0][idx] = 0.f;
    g_c[idx] = 0.f;
}

// ---------------- fused per-step kernel ----------------
// grid = 128 CTAs (8 batches x 16 node-tiles of 32), block = 256
// smem (floats): sh_h[32][132] | sh_a[32][36] | sh_H[32][132] | sh_ho[32][132] | sh_w[16][512]
#define SM_FLOATS (4224 + 1152 + 4224 + 4224 + 8192)

__global__ __launch_bounds__(256) void k_step(int t, const float* __restrict__ Wout,
                                              const float* __restrict__ bout,
                                              float* __restrict__ out) {
    extern __shared__ float sm[];
    float* sh_h  = sm;            // staging for h k-tiles; reused later as h_new tile
    float* sh_a  = sm + 4224;
    float* sh_H  = sm + 5376;
    float* sh_ho = sm + 9600;
    float* sh_w  = sm + 13824;

    const float* hprev = g_h[(t + 1) & 1];
    float*       hnew  = g_h[t & 1];

    int tid = threadIdx.x;
    int b  = blockIdx.x >> 4;
    int n0 = (blockIdx.x & 15) << 5;
    const float* hb = hprev + (size_t)b * NN * NH2;

    // preload this tile's own h rows (contiguous 32x128)
    {
        const float4* src = (const float4*)(hb + (size_t)n0 * NH2);
        #pragma unroll
        for (int i = 0; i < 4; i++) {
            int lin = i * 256 + tid;
            float4 v = src[lin];
            int r = lin >> 5, c4 = lin & 31;
            *(float4*)&sh_ho[r * 132 + c4 * 4] = v;
        }
    }

    // ---- Phase A: H(32x128) = An(32x512) @ h(512x128), thread = 4 rows x 4 cols
    int cg = tid & 31, rg = tid >> 5;
    int c0 = cg * 4;
    unsigned long long acc[4][2];
    #pragma unroll
    for (int i = 0; i < 4; i++) { acc[i][0] = 0ull; acc[i][1] = 0ull; }

    for (int k0 = 0; k0 < NN; k0 += 32) {
        const float4* hs = (const float4*)(hb + (size_t)k0 * NH2);
        #pragma unroll
        for (int i = 0; i < 4; i++) {
            int lin = i * 256 + tid;
            float4 v = hs[lin];
            int r = lin >> 5, c4 = lin & 31;
            *(float4*)&sh_h[r * 132 + c4 * 4] = v;
        }
        {
            int r = tid >> 3, j4 = (tid & 7) * 4;
            float4 av = *(const float4*)(g_An + ((size_t)(b * NN + n0 + r)) * NN + k0 + j4);
            *(float4*)&sh_a[r * 36 + j4] = av;
        }
        __syncthreads();
        #pragma unroll
        for (int kk = 0; kk < 32; kk += 4) {
            float4 ar[4];
            #pragma unroll
            for (int i = 0; i < 4; i++) ar[i] = *(const float4*)&sh_a[(rg + 8 * i) * 36 + kk];
            #pragma unroll
            for (int q = 0; q < 4; q++) {
                const float* hr = &sh_h[(kk + q) * 132 + c0];
                unsigned long long h01 = *(const unsigned long long*)hr;
                unsigned long long h23 = *(const unsigned long long*)(hr + 2);
                #pragma unroll
                for (int i = 0; i < 4; i++) {
                    float aq = (q == 0) ? ar[i].x : (q == 1) ? ar[i].y
                             : (q == 2) ? ar[i].z : ar[i].w;
                    unsigned long long ap = pack2(aq);
                    fma2(acc[i][0], ap, h01);
                    fma2(acc[i][1], ap, h23);
                }
            }
        }
        __syncthreads();
    }
    #pragma unroll
    for (int i = 0; i < 4; i++) {
        *(unsigned long long*)&sh_H[(rg + 8 * i) * 132 + c0]     = acc[i][0];
        *(unsigned long long*)&sh_H[(rg + 8 * i) * 132 + c0 + 2] = acc[i][1];
    }

    // ---- Phase B: z(32x512) = esW + H@Wc + h_own@Wh2, thread = 1 row x 64 interleaved cols
    int row = tid >> 3, chunk = tid & 7;
    int node = b * NN + n0 + row;
    unsigned long long z[32];
    {
        const ulonglong2* ez = (const ulonglong2*)(g_esW + (size_t)node * NZ);
        #pragma unroll
        for (int j = 0; j < 16; j++) {
            ulonglong2 v = ez[chunk + 8 * j];
            z[2 * j] = v.x; z[2 * j + 1] = v.y;
        }
    }
    #pragma unroll
    for (int pass = 0; pass < 2; pass++) {
        const float* Wsrc = pass ? g_Wh2 : g_Wc;
        const float* Asrc = pass ? sh_ho : sh_H;
        for (int k0 = 0; k0 < NH2; k0 += 16) {
            __syncthreads();
            const float4* ws = (const float4*)(Wsrc + (size_t)k0 * NZ);
            #pragma unroll
            for (int i = 0; i < 8; i++)
                ((float4*)sh_w)[i * 256 + tid] = ws[i * 256 + tid];
            __syncthreads();
            #pragma unroll
            for (int kk = 0; kk < 16; kk++) {
                unsigned long long ap = pack2(Asrc[row * 132 + k0 + kk]);
                const ulonglong2* wrow = (const ulonglong2*)(sh_w + kk * NZ);
                #pragma unroll
                for (int j = 0; j < 16; j++) {
                    ulonglong2 wv = wrow[chunk + 8 * j];
                    fma2(z[2 * j],     ap, wv.x);
                    fma2(z[2 * j + 1], ap, wv.y);
                }
            }
        }
    }

    // ---- Gates: cols are packed 4*ch+{i,f,g,o}, so each ull pair is one channel
    float* hn_s = sh_h;   // reuse phase-A staging buffer for h_new tile
    {
        float* cptr = g_c + (size_t)node * NH2;
        float* hw = hnew + (size_t)node * NH2;
        #pragma unroll
        for (int j = 0; j < 16; j++) {
            int ch = chunk + 8 * j;
            float2 p0 = unpack2(z[2 * j]);
            float2 p1 = unpack2(z[2 * j + 1]);
            float it = 1.f / (1.f + __expf(-p0.x));
            float ft = 1.f / (1.f + __expf(-p0.y));
            float gt = tanhf(p1.x);
            float ot = 1.f / (1.f + __expf(-p1.y));
            float cn = ft * cptr[ch] + it * gt;
            float hv = ot * tanhf(cn);
            cptr[ch] = cn;
            hw[ch] = hv;
            hn_s[row * 132 + ch] = hv;
        }
    }
    __syncthreads();

    // ---- Phase C: out[t] = out[t-1] + h_new @ Wout + bout (stage Wout in smem)
    #pragma unroll
    for (int i = 0; i < 8; i++)
        ((float4*)sh_w)[i * 256 + tid] = ((const float4*)Wout)[i * 256 + tid];
    __syncthreads();
    {
        int cc0 = chunk * 8;
        unsigned long long oa[4] = {0ull, 0ull, 0ull, 0ull};
        #pragma unroll
        for (int k = 0; k < NH2; k++) {
            unsigned long long ap = pack2(hn_s[row * 132 + k]);
            const ulonglong2* wr = (const ulonglong2*)(sh_w + k * 64 + cc0);
            ulonglong2 w0 = wr[0], w1 = wr[1];
            fma2(oa[0], ap, w0.x); fma2(oa[1], ap, w0.y);
            fma2(oa[2], ap, w1.x); fma2(oa[3], ap, w1.y);
        }
        size_t pbase = (((size_t)node) * TT + (t - 1)) * NIN + cc0;
        size_t obase = (((size_t)node) * TT + t) * NIN + cc0;
        float4 pv0 = *(const float4*)(out + pbase);
        float4 pv1 = *(const float4*)(out + pbase + 4);
        float4 bo0 = *(const float4*)(bout + cc0);
        float4 bo1 = *(const float4*)(bout + cc0 + 4);
        float2 r0 = unpack2(oa[0]), r1 = unpack2(oa[1]);
        float2 r2 = unpack2(oa[2]), r3 = unpack2(oa[3]);
        float4 w0 = make_float4(pv0.x + r0.x + bo0.x, pv0.y + r0.y + bo0.y,
                                pv0.z + r1.x + bo0.z, pv0.w + r1.y + bo0.w);
        float4 w1 = make_float4(pv1.x + r2.x + bo1.x, pv1.y + r2.y + bo1.y,
                                pv1.z + r3.x + bo1.z, pv1.w + r3.y + bo1.w);
        *(float4*)(out + obase)     = w0;
        *(float4*)(out + obase + 4) = w1;
    }
}

// ---------------- launch ----------------
extern "C" void kernel_launch(void* const* d_in, const int* in_sizes, int n_in,
                              void* d_out, int out_size) {
    (void)in_sizes; (void)n_in; (void)out_size;
    const float* X    = (const float*)d_in[0];
    const float* A    = (const float*)d_in[1];
    const float* Wse  = (const float*)d_in[2];
    const float* bse  = (const float*)d_in[3];
    const float* Wpe  = (const float*)d_in[4];
    const float* bpe  = (const float*)d_in[5];
    const float* Wii  = (const float*)d_in[6];
    const float* bii  = (const float*)d_in[7];
    const float* Whi  = (const float*)d_in[8];
    const float* bhi  = (const float*)d_in[9];
    const float* Wif  = (const float*)d_in[10];
    const float* bif  = (const float*)d_in[11];
    const float* Whf  = (const float*)d_in[12];
    const float* bhf  = (const float*)d_in[13];
    const float* Wig  = (const float*)d_in[14];
    const float* big  = (const float*)d_in[15];
    const float* Whg  = (const float*)d_in[16];
    const float* bhg  = (const float*)d_in[17];
    const float* Wio  = (const float*)d_in[18];
    const float* bio  = (const float*)d_in[19];
    const float* Who  = (const float*)d_in[20];
    const float* bho  = (const float*)d_in[21];
    const float* Wout = (const float*)d_in[22];
    const float* bout = (const float*)d_in[23];
    float* out = (float*)d_out;

    cudaFuncSetAttribute(k_step, cudaFuncAttributeMaxDynamicSharedMemorySize,
                         SM_FLOATS * (int)sizeof(float));

    k_dinv<<<BB * NN, 128>>>(A);
    k_an<<<(BB * NN * NN) / 256, 256>>>(A);
    k_es<<<(NODES * NE) / 256, 256>>>(X, Wse, bse, out);
    k_wpack<<<(NE * NZ) / 256, 256>>>(Wpe, bpe, Wii, bii, Whi, bhi, Wif, bif,
                                      Whf, bhf, Wig, big, Whg, bhg,
                                      Wio, bio, Who, bho);
    k_esw<<<(NODES * NZ) / 256, 256>>>(Wii, Wif, Wig, Wio);
    k_zero<<<(NODES * NH2) / 256, 256>>>();

    for (int t = 1; t < TT; t++) {
        k_step<<<128, 256, SM_FLOATS * (int)sizeof(float)>>>(t, Wout, bout, out);
    }
}

// round 6
// speedup vs baseline: 2.6314x; 2.6314x over previous
#include <cuda_runtime.h>
#include <cuda_bf16.h>
#include <math.h>
#include <stdint.h>

#define BB 8
#define NN 512
#define TT 64
#define NIN 64
#define NE 128
#define NH 128
#define NZ 512
#define NODES (BB*NN)   // 4096

// ---------------- persistent device scratch ----------------
__device__ float g_dinv[BB*NN];
__device__ __nv_bfloat16 g_An_hi[BB*NN*NN], g_An_lo[BB*NN*NN];   // 4MB each
__device__ __nv_bfloat16 g_h_hi[2][NODES*NH], g_h_lo[2][NODES*NH]; // ping-pong h
__device__ float g_es[NODES*NE];
__device__ float g_esW[NODES*NZ];          // step-invariant gate term (packed cols)
__device__ float g_b0[NZ];
__device__ __nv_bfloat16 g_Wz_hi[256*NZ], g_Wz_lo[256*NZ];       // [k][n] k:0-127 Wc,128-255 Wh
__device__ float g_c[NODES*NH];

// ---------------- helpers ----------------
__device__ __forceinline__ uint32_t smem_u32(const void* p) {
    uint32_t a;
    asm("{ .reg .u64 t; cvta.to.shared.u64 t, %1; cvt.u32.u64 %0, t; }" : "=r"(a) : "l"(p));
    return a;
}
__device__ __forceinline__ void ldsm4(uint32_t* r, uint32_t addr) {
    asm volatile("ldmatrix.sync.aligned.m8n8.x4.shared.b16 {%0,%1,%2,%3}, [%4];"
        : "=r"(r[0]), "=r"(r[1]), "=r"(r[2]), "=r"(r[3]) : "r"(addr));
}
__device__ __forceinline__ void ldsm2t(uint32_t* r, uint32_t addr) {
    asm volatile("ldmatrix.sync.aligned.m8n8.x2.trans.shared.b16 {%0,%1}, [%2];"
        : "=r"(r[0]), "=r"(r[1]) : "r"(addr));
}
__device__ __forceinline__ void mma_bf16(float* d, const uint32_t* a, const uint32_t* b) {
    asm volatile("mma.sync.aligned.m16n8k16.row.col.f32.bf16.bf16.f32 "
        "{%0,%1,%2,%3}, {%4,%5,%6,%7}, {%8,%9}, {%0,%1,%2,%3};"
        : "+f"(d[0]), "+f"(d[1]), "+f"(d[2]), "+f"(d[3])
        : "r"(a[0]), "r"(a[1]), "r"(a[2]), "r"(a[3]), "r"(b[0]), "r"(b[1]));
}
__device__ __forceinline__ void split_bf(float x, __nv_bfloat16& h, __nv_bfloat16& l) {
    h = __float2bfloat16(x);
    l = __float2bfloat16(x - __bfloat162float(h));
}
__device__ __forceinline__ float sigf(float x) { return 1.f / (1.f + __expf(-x)); }

// ---------------- setup kernels ----------------
__global__ void k_dinv(const float* __restrict__ A) {
    int row = blockIdx.x;
    const float* ap = A + (size_t)row * NN;
    float s = 0.f;
    for (int i = threadIdx.x; i < NN; i += 128) s += ap[i];
    __shared__ float red[4];
    for (int o = 16; o; o >>= 1) s += __shfl_xor_sync(0xffffffffu, s, o);
    if ((threadIdx.x & 31) == 0) red[threadIdx.x >> 5] = s;
    __syncthreads();
    if (threadIdx.x == 0) {
        float d = red[0] + red[1] + red[2] + red[3];
        g_dinv[row] = d > 0.f ? rsqrtf(d) : 0.f;
    }
}

__global__ void k_an(const float* __restrict__ A) {
    int idx = blockIdx.x * 256 + threadIdx.x;
    int b = idx / (NN * NN);
    int r = (idx / NN) % NN;
    int m = idx % NN;
    float v = A[idx] * g_dinv[b * NN + r] * g_dinv[b * NN + m];
    split_bf(v, g_An_hi[idx], g_An_lo[idx]);
}

__global__ void k_es(const float* __restrict__ X, const float* __restrict__ Wse,
                     const float* __restrict__ bse, float* __restrict__ out) {
    int idx = blockIdx.x * 256 + threadIdx.x;
    int node = idx >> 7, j = idx & 127;
    const float* x0 = X + (size_t)node * TT * NIN;
    float acc = bse[j];
    #pragma unroll
    for (int q = 0; q < NIN; q++) acc += x0[q] * Wse[q * NE + j];
    g_es[idx] = acc;
    if (j < NIN) out[(size_t)node * TT * NIN + j] = x0[j];
}

__global__ void k_wz(const float* __restrict__ Wpe, const float* __restrict__ bpe,
    const float* __restrict__ Wii, const float* __restrict__ bii,
    const float* __restrict__ Whi, const float* __restrict__ bhi,
    const float* __restrict__ Wif, const float* __restrict__ bif,
    const float* __restrict__ Whf, const float* __restrict__ bhf,
    const float* __restrict__ Wig, const float* __restrict__ big,
    const float* __restrict__ Whg, const float* __restrict__ bhg,
    const float* __restrict__ Wio, const float* __restrict__ bio,
    const float* __restrict__ Who, const float* __restrict__ bho) {
    int idx = blockIdx.x * 256 + threadIdx.x;   // 256*512 threads, [k][n]
    int k = idx >> 9, n = idx & 511;
    int ch = n >> 2, g = n & 3;
    const float* Wg  = g == 0 ? Wii : g == 1 ? Wif : g == 2 ? Wig : Wio;
    const float* Whx = g == 0 ? Whi : g == 1 ? Whf : g == 2 ? Whg : Who;
    float v;
    if (k < 128) {
        v = 0.f;
        for (int p = 0; p < NE; p++) v += Wpe[k * NE + p] * Wg[(NE + p) * NH + ch];
    } else {
        v = Whx[(k - 128) * NH + ch];
    }
    split_bf(v, g_Wz_hi[idx], g_Wz_lo[idx]);
    if (k == 0) {
        const float* bg  = g == 0 ? bii : g == 1 ? bif : g == 2 ? big : bio;
        const float* bhx = g == 0 ? bhi : g == 1 ? bhf : g == 2 ? bhg : bho;
        float bv = bg[ch] + bhx[ch];
        for (int p = 0; p < NE; p++) bv += bpe[p] * Wg[(NE + p) * NH + ch];
        g_b0[n] = bv;
    }
}

__global__ void k_esw(const float* __restrict__ Wii, const float* __restrict__ Wif,
                      const float* __restrict__ Wig, const float* __restrict__ Wio) {
    int idx = blockIdx.x * 256 + threadIdx.x;
    int node = idx >> 9, j = idx & 511;
    int ch = j >> 2, g = j & 3;
    const float* Wg = g == 0 ? Wii : g == 1 ? Wif : g == 2 ? Wig : Wio;
    const float* e = g_es + (size_t)node * NE;
    float acc = g_b0[j];
    for (int p = 0; p < NE; p++) acc += e[p] * Wg[p * NH + ch];
    g_esW[idx] = acc;
}

__global__ void k_zero() {
    int idx = blockIdx.x * 256 + threadIdx.x;   // NODES*NH
    g_c[idx] = 0.f;
    __nv_bfloat16 z = __float2bfloat16(0.f);
    g_h_hi[0][idx] = z;
    g_h_lo[0][idx] = z;
}

// ---------------- smem layout (bytes) ----------------
// HH: [H|h] A-operand, 32 rows x 264 bf16 (cols 0-127 H, 128-255 h), hi+lo
#define S_HH_HI   0u
#define S_HH_LO   16896u
// R1 (phase A): An chunk [32][136]b hi/lo, h chunk [128][136]b hi/lo
#define S_AN_HI   33792u
#define S_AN_LO   42496u
#define S_HC_HI   51200u
#define S_HC_LO   86016u
// R1 (phase B): W tile [64][264]b hi/lo
#define S_W_HI    33792u
#define S_W_LO    67584u
// R1 (phase C): Wout f32 [128][68]
#define S_WO      33792u
// z-buffer f32 [32][260]
#define S_ZB      120832u
// h_new f32 [32][133]
#define S_HN      154112u
#define SMEM_TOT  171136

// ---------------- fused per-step kernel ----------------
// grid 128 (node tiles of 32), block 256 (8 warps)
__global__ __launch_bounds__(256, 1) void k_step(int t, const float* __restrict__ Wout,
                                                 const float* __restrict__ bout,
                                                 float* __restrict__ out) {
    extern __shared__ char sm[];
    uint32_t smb = smem_u32(sm);
    int tid = threadIdx.x, lane = tid & 31, w = tid >> 5;
    long node0 = (long)blockIdx.x * 32;
    int b = (int)(node0 >> 9);
    int pp = (t + 1) & 1, pn = t & 1;
    const __nv_bfloat16* hp_hi = g_h_hi[pp];
    const __nv_bfloat16* hp_lo = g_h_lo[pp];

    // ldmatrix lane address components
    int a_r = (lane & 7) + ((lane >> 3) & 1) * 8;   // row offset within m16k16 A tile
    int a_c = ((lane >> 4) & 1) * 8;                // k-col offset
    int b_r = lane & 15;                            // row offset for B (trans)

    // ---- copy own 32 h rows into HH cols 128-255 (hi/lo) ----
    {
        #pragma unroll
        for (int i = 0; i < 2; i++) {
            int idx = i * 256 + tid;
            int row = idx >> 4, seg = idx & 15;
            const uint4* sH = (const uint4*)(hp_hi + (node0 + row) * NH) + seg;
            const uint4* sL = (const uint4*)(hp_lo + (node0 + row) * NH) + seg;
            *(uint4*)(sm + S_HH_HI + (row * 264 + 128 + seg * 8) * 2) = *sH;
            *(uint4*)(sm + S_HH_LO + (row * 264 + 128 + seg * 8) * 2) = *sL;
        }
    }

    // ---- Phase A: H = An @ h  (M=32, N=128, K=512; 4 K-chunks of 128) ----
    int wm = w >> 2, wn = w & 3;        // 2 m-strips x 4 n-strips(32ch)
    float accA[4][4];
    #pragma unroll
    for (int nt = 0; nt < 4; nt++)
        #pragma unroll
        for (int q = 0; q < 4; q++) accA[nt][q] = 0.f;

    for (int c = 0; c < 4; c++) {
        // load An chunk [32][128] hi/lo
        #pragma unroll
        for (int i = 0; i < 2; i++) {
            int idx = i * 256 + tid;
            int row = idx >> 4, seg = idx & 15;
            const uint4* sH = (const uint4*)(g_An_hi + (node0 + row) * (long)NN + c * 128) + seg;
            const uint4* sL = (const uint4*)(g_An_lo + (node0 + row) * (long)NN + c * 128) + seg;
            *(uint4*)(sm + S_AN_HI + (row * 136 + seg * 8) * 2) = *sH;
            *(uint4*)(sm + S_AN_LO + (row * 136 + seg * 8) * 2) = *sL;
        }
        // load h chunk [128][128] hi/lo
        #pragma unroll
        for (int i = 0; i < 8; i++) {
            int idx = i * 256 + tid;
            int row = idx >> 4, seg = idx & 15;
            long nsrc = (long)b * NN + c * 128 + row;
            const uint4* sH = (const uint4*)(hp_hi + nsrc * NH) + seg;
            const uint4* sL = (const uint4*)(hp_lo + nsrc * NH) + seg;
            *(uint4*)(sm + S_HC_HI + (row * 136 + seg * 8) * 2) = *sH;
            *(uint4*)(sm + S_HC_LO + (row * 136 + seg * 8) * 2) = *sL;
        }
        __syncthreads();
        #pragma unroll
        for (int kk = 0; kk < 8; kk++) {
            int k = kk * 16;
            uint32_t aH[4], aL[4];
            uint32_t aoff = ((wm * 16 + a_r) * 136 + k + a_c) * 2;
            ldsm4(aH, smb + S_AN_HI + aoff);
            ldsm4(aL, smb + S_AN_LO + aoff);
            #pragma unroll
            for (int nt = 0; nt < 4; nt++) {
                uint32_t bH[2], bL[2];
                uint32_t boff = ((k + b_r) * 136 + wn * 32 + nt * 8) * 2;
                ldsm2t(bH, smb + S_HC_HI + boff);
                ldsm2t(bL, smb + S_HC_LO + boff);
                mma_bf16(accA[nt], aH, bH);
                mma_bf16(accA[nt], aH, bL);
                mma_bf16(accA[nt], aL, bH);
            }
        }
        __syncthreads();
    }
    // epilogue: split H into HH cols 0-127
    {
        int r0 = wm * 16 + (lane >> 2), r1 = r0 + 8;
        #pragma unroll
        for (int nt = 0; nt < 4; nt++) {
            int col = wn * 32 + nt * 8 + (lane & 3) * 2;
            __nv_bfloat16 h0, l0, h1, l1;
            split_bf(accA[nt][0], h0, l0); split_bf(accA[nt][1], h1, l1);
            __nv_bfloat162 ph; ph.x = h0; ph.y = h1;
            __nv_bfloat162 pl; pl.x = l0; pl.y = l1;
            *(__nv_bfloat162*)(sm + S_HH_HI + (r0 * 264 + col) * 2) = ph;
            *(__nv_bfloat162*)(sm + S_HH_LO + (r0 * 264 + col) * 2) = pl;
            split_bf(accA[nt][2], h0, l0); split_bf(accA[nt][3], h1, l1);
            ph.x = h0; ph.y = h1; pl.x = l0; pl.y = l1;
            *(__nv_bfloat162*)(sm + S_HH_HI + (r1 * 264 + col) * 2) = ph;
            *(__nv_bfloat162*)(sm + S_HH_LO + (r1 * 264 + col) * 2) = pl;
        }
    }

    // ---- Phase B: z = esW + [H|h] @ Wz  (2 n-chunks of 256; K=256) ----
    float* zb = (float*)(sm + S_ZB);
    float* hn = (float*)(sm + S_HN);
    for (int nc = 0; nc < 2; nc++) {
        float accB[8][4];
        #pragma unroll
        for (int nt = 0; nt < 8; nt++)
            #pragma unroll
            for (int q = 0; q < 4; q++) accB[nt][q] = 0.f;

        for (int kc = 0; kc < 4; kc++) {
            __syncthreads();   // protect W tile / zb reuse
            // load W tile [64][256] hi/lo
            #pragma unroll
            for (int i = 0; i < 8; i++) {
                int idx = i * 256 + tid;
                int row = idx >> 5, seg = idx & 31;
                long src = (long)(kc * 64 + row) * NZ + nc * 256;
                const uint4* sH = (const uint4*)(g_Wz_hi + src) + seg;
                const uint4* sL = (const uint4*)(g_Wz_lo + src) + seg;
                *(uint4*)(sm + S_W_HI + (row * 264 + seg * 8) * 2) = *sH;
                *(uint4*)(sm + S_W_LO + (row * 264 + seg * 8) * 2) = *sL;
            }
            __syncthreads();
            #pragma unroll
            for (int kk = 0; kk < 4; kk++) {
                int gk = kc * 64 + kk * 16;   // col in HH
                int k  = kk * 16;             // row in W tile
                uint32_t aH[4], aL[4];
                uint32_t aoff = ((wm * 16 + a_r) * 264 + gk + a_c) * 2;
                ldsm4(aH, smb + S_HH_HI + aoff);
                ldsm4(aL, smb + S_HH_LO + aoff);
                #pragma unroll
                for (int nt = 0; nt < 8; nt++) {
                    uint32_t bH[2], bL[2];
                    uint32_t boff = ((k + b_r) * 264 + wn * 64 + nt * 8) * 2;
                    ldsm2t(bH, smb + S_W_HI + boff);
                    ldsm2t(bL, smb + S_W_LO + boff);
                    mma_bf16(accB[nt], aH, bH);
                    mma_bf16(accB[nt], aH, bL);
                    mma_bf16(accB[nt], aL, bH);
                }
            }
        }
        __syncthreads();
        // accums -> z buffer
        {
            int r0 = wm * 16 + (lane >> 2), r1 = r0 + 8;
            #pragma unroll
            for (int nt = 0; nt < 8; nt++) {
                int col = wn * 64 + nt * 8 + (lane & 3) * 2;
                zb[r0 * 260 + col]     = accB[nt][0];
                zb[r0 * 260 + col + 1] = accB[nt][1];
                zb[r1 * 260 + col]     = accB[nt][2];
                zb[r1 * 260 + col + 1] = accB[nt][3];
            }
        }
        __syncthreads();
        // gates: thread -> (row = tid>>3, 8 channels)
        {
            int row = tid >> 3, g8 = tid & 7;
            long node = node0 + row;
            int chb = nc * 64 + g8 * 8;
            float cbuf[8];
            *(float4*)(cbuf)     = *(const float4*)(g_c + node * NH + chb);
            *(float4*)(cbuf + 4) = *(const float4*)(g_c + node * NH + chb + 4);
            __nv_bfloat16 hh[8], hl[8];
            #pragma unroll
            for (int q = 0; q < 8; q++) {
                int colz = g8 * 32 + 4 * q;
                float4 z4 = *(const float4*)(zb + row * 260 + colz);
                float4 e4 = *(const float4*)(g_esW + node * NZ + nc * 256 + colz);
                float it = sigf(z4.x + e4.x);
                float ft = sigf(z4.y + e4.y);
                float gt = tanhf(z4.z + e4.z);
                float ot = sigf(z4.w + e4.w);
                float cn = ft * cbuf[q] + it * gt;
                float hv = ot * tanhf(cn);
                cbuf[q] = cn;
                hn[row * 133 + chb + q] = hv;
                split_bf(hv, hh[q], hl[q]);
            }
            *(float4*)(g_c + node * NH + chb)     = *(const float4*)(cbuf);
            *(float4*)(g_c + node * NH + chb + 4) = *(const float4*)(cbuf + 4);
            *(uint4*)(g_h_hi[pn] + node * NH + chb) = *(const uint4*)hh;
            *(uint4*)(g_h_lo[pn] + node * NH + chb) = *(const uint4*)hl;
        }
    }
    __syncthreads();

    // ---- Phase C: out[t] = out[t-1] + h_new @ Wout + bout (exact fp32) ----
    float* wo = (float*)(sm + S_WO);
    #pragma unroll
    for (int i = 0; i < 8; i++) {
        int idx = i * 256 + tid;
        int row = idx >> 4, c4 = (idx & 15) * 4;
        *(float4*)(wo + row * 68 + c4) = *(const float4*)(Wout + row * NIN + c4);
    }
    __syncthreads();
    {
        int row = tid >> 3, c8 = (tid & 7) * 8;
        long node = node0 + row;
        float o[8];
        *(float4*)(o)     = *(const float4*)(bout + c8);
        *(float4*)(o + 4) = *(const float4*)(bout + c8 + 4);
        #pragma unroll 4
        for (int k = 0; k < NH; k++) {
            float hv = hn[row * 133 + k];
            float4 w0 = *(const float4*)(wo + k * 68 + c8);
            float4 w1 = *(const float4*)(wo + k * 68 + c8 + 4);
            o[0] += hv * w0.x; o[1] += hv * w0.y;
            o[2] += hv * w0.z; o[3] += hv * w0.w;
            o[4] += hv * w1.x; o[5] += hv * w1.y;
            o[6] += hv * w1.z; o[7] += hv * w1.w;
        }
        long pb = (node * TT + (t - 1)) * NIN + c8;
        long ob = (node * TT + t) * NIN + c8;
        float4 p0 = *(const float4*)(out + pb);
        float4 p1 = *(const float4*)(out + pb + 4);
        float4 w0 = make_float4(p0.x + o[0], p0.y + o[1], p0.z + o[2], p0.w + o[3]);
        float4 w1 = make_float4(p1.x + o[4], p1.y + o[5], p1.z + o[6], p1.w + o[7]);
        *(float4*)(out + ob)     = w0;
        *(float4*)(out + ob + 4) = w1;
    }
}

// ---------------- launch ----------------
extern "C" void kernel_launch(void* const* d_in, const int* in_sizes, int n_in,
                              void* d_out, int out_size) {
    (void)in_sizes; (void)n_in; (void)out_size;
    const float* X    = (const float*)d_in[0];
    const float* A    = (const float*)d_in[1];
    const float* Wse  = (const float*)d_in[2];
    const float* bse  = (const float*)d_in[3];
    const float* Wpe  = (const float*)d_in[4];
    const float* bpe  = (const float*)d_in[5];
    const float* Wii  = (const float*)d_in[6];
    const float* bii  = (const float*)d_in[7];
    const float* Whi  = (const float*)d_in[8];
    const float* bhi  = (const float*)d_in[9];
    const float* Wif  = (const float*)d_in[10];
    const float* bif  = (const float*)d_in[11];
    const float* Whf  = (const float*)d_in[12];
    const float* bhf  = (const float*)d_in[13];
    const float* Wig  = (const float*)d_in[14];
    const float* big  = (const float*)d_in[15];
    const float* Whg  = (const float*)d_in[16];
    const float* bhg  = (const float*)d_in[17];
    const float* Wio  = (const float*)d_in[18];
    const float* bio  = (const float*)d_in[19];
    const float* Who  = (const float*)d_in[20];
    const float* bho  = (const float*)d_in[21];
    const float* Wout = (const float*)d_in[22];
    const float* bout = (const float*)d_in[23];
    float* out = (float*)d_out;

    cudaFuncSetAttribute(k_step, cudaFuncAttributeMaxDynamicSharedMemorySize, SMEM_TOT);

    k_dinv<<<BB * NN, 128>>>(A);
    k_an<<<(BB * NN * NN) / 256, 256>>>(A);
    k_es<<<(NODES * NE) / 256, 256>>>(X, Wse, bse, out);
    k_wz<<<(256 * NZ) / 256, 256>>>(Wpe, bpe, Wii, bii, Whi, bhi, Wif, bif,
                                    Whf, bhf, Wig, big, Whg, bhg,
                                    Wio, bio, Who, bho);
    k_esw<<<(NODES * NZ) / 256, 256>>>(Wii, Wif, Wig, Wio);
    k_zero<<<(NODES * NH) / 256, 256>>>();

    for (int t = 1; t < TT; t++) {
        k_step<<<128, 256, SMEM_TOT>>>(t, Wout, bout, out);
    }
}